// round 8
// baseline (speedup 1.0000x reference)
#include <cuda_runtime.h>
#include <math.h>

#define NIMG 256        // B*N = 64*4
#define NTHREADS 1024

typedef unsigned long long ull;

// ---- dynamic shared layout (bytes) ----
#define SM_CSB  0                    // float2 [49] base col   = 512 (padded)
#define SM_SDB  (SM_CSB + 512)       // float4 [49][24]        = 18816
#define SM_WT   (SM_SDB + 18816)     // float2 [256]           = 2048
#define SM_WP   (SM_WT + 2048)       // ulonglong2 [768]       = 12288 (3x dup)
#define SM_SGDG (SM_WP + 12288)      // float4 [24][288]       = 110592
#define SM_G0   (SM_SGDG + 110592)   // float2 [288]           = 2304
#define SM_CROP (SM_G0 + 2304)       // float  [4096]          = 16384
#define SM_RED  (SM_CROP + 16384)    // float  [32]            = 128
#define SM_TOTAL (SM_RED + 128)      // 163072 bytes

#define GSTRIDE 288

extern __shared__ char smem_raw[];

#define FMA2(d, a, b, c) \
    asm("fma.rn.f32x2 %0, %1, %2, %3;" : "=l"(d) : "l"(a), "l"(b), "l"(c))

__device__ __forceinline__ float2 u2f2(ull v) {
    float2 r;
    asm("mov.b64 {%0, %1}, %2;" : "=f"(r.x), "=f"(r.y) : "l"(v));
    return r;
}
__device__ __forceinline__ ull splat2(float f) {
    ull r;
    asm("mov.b64 %0, {%1, %1};" : "=l"(r) : "f"(f));
    return r;
}

__device__ __forceinline__ float2 pupil_pt(int a, int b, float x, float y,
                                           float z, const float* __restrict__ ph)
{
    float us = (float)(2 * a - 63) * (1.0f / 47.25f);
    float vs = (float)(2 * b - 63) * (1.0f / 47.25f);
    float R  = sqrtf(us * us + vs * vs);
    if (R > 1.0f) return make_float2(0.0f, 0.0f);
    float prop = sqrtf(fmaxf(1.0f - R * R, 0.0f));
    float psi = ph[a * 64 + b] + prop * z
              - (6.283185307179586f / 256.0f)
                * ((float)(a - 32) * x + (float)(b - 32) * y);
    float sn, cs;
    __sincosf(psi, &sn, &cs);
    return make_float2(cs, sn);
}

__global__ void __launch_bounds__(NTHREADS, 1)
render_kernel(const float* __restrict__ X,  const float* __restrict__ Y,
              const float* __restrict__ Z,  const float* __restrict__ Aa,
              const float* __restrict__ Bg, const float* __restrict__ P,
              const float* __restrict__ phase0,
              float* __restrict__ out)
{
    float2*     CsB  = (float2*)    (smem_raw + SM_CSB);
    float4*     SDB  = (float4*)    (smem_raw + SM_SDB);
    float2*     Wt   = (float2*)    (smem_raw + SM_WT);
    ulonglong2* Wp   = (ulonglong2*)(smem_raw + SM_WP);
    float4*     SGDG = (float4*)    (smem_raw + SM_SGDG);
    float2*     G0   = (float2*)    (smem_raw + SM_G0);
    float*      crop = (float*)     (smem_raw + SM_CROP);
    float*      red  = (float*)     (smem_raw + SM_RED);

    const int img  = blockIdx.x;
    const int tid  = threadIdx.x;
    const int lane = tid & 31;
    const int warp = tid >> 5;     // 0..31

    const float x = X[img], y = Y[img], z = Z[img];

    // ---- twiddle tables: W[k] = exp(2*pi*i*k/256), packed table 3x dup ----
    if (tid < 256) {
        float s, c;
        sincospif((float)tid * (1.0f / 128.0f), &s, &c);
        Wt[tid] = make_float2(c, s);
        ulonglong2 w2 = make_ulonglong2(splat2(c), splat2(s));
        Wp[tid] = w2; Wp[tid + 256] = w2; Wp[tid + 512] = w2;
    }

    // ---- fused Phase A + SDB: thread per (row r, fold q) pair ----
    // SDB[r][q-1] = (S.r, S.i, D.i, D.r) with S/D = C[a][32+q] +/- C[a][32-q]
    for (int idx = tid; idx < 49 * 25; idx += NTHREADS) {
        int r = idx / 25;
        int q = idx - r * 25;               // 0..24
        int a = r + 8;
        if (q == 0) {
            CsB[r] = pupil_pt(a, 32, x, y, z, phase0);
        } else {
            float2 cu = pupil_pt(a, 32 + q, x, y, z, phase0);
            float2 cd = pupil_pt(a, 32 - q, x, y, z, phase0);
            SDB[r * 24 + (q - 1)] = make_float4(cu.x + cd.x, cu.y + cd.y,
                                                cu.y - cd.y, cu.x - cd.x);
        }
    }
    __syncthreads();

    // ---- Phase B (packed f32x2): row-paired, v-folded column DFT ----
    // elliptical trip bound: columns beyond pupil disk are exactly zero
    for (int i = 0; i < 4; i++) {
        int t = warp + 32 * i;
        if (t >= 100) break;
        int m  = t >> 2;
        int vb = t & 3;
        int v  = (vb << 5) + lane;          // 0..127

        int mm = 2 * m - 1;
        float wrad = 2232.5625f - (float)(mm * mm);
        int qe = min(24, (int)((sqrtf(wrad) - 1.0f) * 0.5f) + 2);

        float2 w0 = Wt[v];
        ull CC  = splat2(w0.x), SS  = splat2(w0.y);
        ull RC  = CC,           RS  = SS;
        ull NRS = splat2(-w0.y);
        const ull ZERO = 0;

        ull ACu = 0, ASu = 0, ACd = 0, ASd = 0;
        const ulonglong2* sup = (const ulonglong2*)(SDB + (24 + m) * 24);
        const ulonglong2* sdn = (const ulonglong2*)(SDB + (24 - m) * 24);

        if (m == 0) {
            #pragma unroll 4
            for (int mb = 0; mb < qe; mb++) {
                ulonglong2 sv = sup[mb];
                FMA2(ACu, CC, sv.x, ACu);
                FMA2(ASu, SS, sv.y, ASu);
                ull t1, t2;
                FMA2(t1, CC, RC, ZERO); FMA2(t2, CC, RS, ZERO);
                FMA2(CC, SS, NRS, t1);  FMA2(SS, SS, RC, t2);
            }
            float2 ac = u2f2(ACu), as = u2f2(ASu);
            float2 base = CsB[24];
            float2 glo = make_float2(base.x + ac.x - as.x, base.y + ac.y + as.y);
            float2 ghi = make_float2(base.x + ac.x + as.x, base.y + ac.y - as.y);
            G0[v] = glo;
            G0[(256 - v) & 255] = ghi;
            if (v < 32) G0[256 + v] = (v == 0) ? ghi : glo;
        } else {
            #pragma unroll 4
            for (int mb = 0; mb < qe; mb++) {
                ulonglong2 sv = sup[mb];
                ulonglong2 dv = sdn[mb];
                FMA2(ACu, CC, sv.x, ACu);
                FMA2(ASu, SS, sv.y, ASu);
                FMA2(ACd, CC, dv.x, ACd);
                FMA2(ASd, SS, dv.y, ASd);
                ull t1, t2;
                FMA2(t1, CC, RC, ZERO); FMA2(t2, CC, RS, ZERO);
                FMA2(CC, SS, NRS, t1);  FMA2(SS, SS, RC, t2);
            }
            float2 acu = u2f2(ACu), asu = u2f2(ASu);
            float2 acd = u2f2(ACd), asd = u2f2(ASd);
            float2 bu = CsB[24 + m];
            float2 bd = CsB[24 - m];
            float2 up_lo = make_float2(bu.x + acu.x - asu.x, bu.y + acu.y + asu.y);
            float2 up_hi = make_float2(bu.x + acu.x + asu.x, bu.y + acu.y - asu.y);
            float2 dn_lo = make_float2(bd.x + acd.x - asd.x, bd.y + acd.y + asd.y);
            float2 dn_hi = make_float2(bd.x + acd.x + asd.x, bd.y + acd.y - asd.y);
            int base = (m - 1) * GSTRIDE;
            int vh = (256 - v) & 255;
            float4 lo4 = make_float4(up_lo.x + dn_lo.x, up_lo.y + dn_lo.y,
                                     up_lo.y - dn_lo.y, up_lo.x - dn_lo.x);
            float4 hi4 = make_float4(up_hi.x + dn_hi.x, up_hi.y + dn_hi.y,
                                     up_hi.y - dn_hi.y, up_hi.x - dn_hi.x);
            SGDG[base + v]  = lo4;
            SGDG[base + vh] = hi4;
            if (v < 32) SGDG[base + 256 + v] = (v == 0) ? hi4 : lo4;
        }
    }

    // ---- v = 128 column (sin = 0, cos = (-1)^q) ----
    if (tid >= 896 && tid < 921) {
        int m = tid - 896;                  // 0..24
        int mm = 2 * m - 1;
        float wrad = 2232.5625f - (float)(mm * mm);
        int qe = min(24, (int)((sqrtf(wrad) - 1.0f) * 0.5f) + 2);
        float2 up = CsB[24 + m];
        float2 dn = CsB[24 - m];
        const float4* sup = SDB + (24 + m) * 24;
        const float4* sdn = SDB + (24 - m) * 24;
        float sgn = -1.f;
        #pragma unroll 4
        for (int mb = 0; mb < qe; mb++) {
            float4 su = sup[mb]; float4 sd = sdn[mb];
            up.x = fmaf(sgn, su.x, up.x); up.y = fmaf(sgn, su.y, up.y);
            dn.x = fmaf(sgn, sd.x, dn.x); dn.y = fmaf(sgn, sd.y, dn.y);
            sgn = -sgn;
        }
        if (m == 0) {
            G0[128] = up;
        } else {
            SGDG[(m - 1) * GSTRIDE + 128] =
                make_float4(up.x + dn.x, up.y + dn.y,
                            up.y - dn.y, up.x - dn.x);
        }
    }
    __syncthreads();

    // ---- Phase C: crop (u-folded, 18 units, tile 4)
    //              + 80u x 96v max-window (30 units, tile 8) ----
    const int iu = (int)(((unsigned)__float2int_rn(x)) & 255u);
    const int iv = (int)(((unsigned)__float2int_rn(y)) & 255u);
    const int wu0 = (iu - 40) & 255;
    const int wv0 = (iv - 48) & 255;

    float lmax = 0.0f;
    const char* wp = (const char*)Wp;

    for (int i = 0; i < 2; i++) {
        int t = warp + 32 * i;
        if (t >= 48) break;

        if (t < 18) {
            // ---- crop unit: ut 0..8 -> u0 = 4*ut; vb 0..1 ----
            int ut = t >> 1;
            int vb = t & 1;
            int v  = vb ? (224 + lane) : lane;
            int u0 = ut << 2;

            int s0i = (u0 + 0) << 4, s1i = (u0 + 1) << 4;
            int s2i = (u0 + 2) << 4, s3i = (u0 + 3) << 4;
            int o0 = s0i, o1 = s1i, o2 = s2i, o3 = s3i;
            ull c0 = 0, s0 = 0, c1 = 0, s1 = 0;
            ull c2 = 0, s2 = 0, c3 = 0, s3 = 0;

            const char* gp = (const char*)(SGDG + v);
            #pragma unroll 3
            for (int mh = 0; mh < 12; mh++) {
                {
                    ulonglong2 gsd = *(const ulonglong2*)gp;
                    gp += GSTRIDE * 16;
                    ulonglong2 w0 = *(const ulonglong2*)(wp + o0);
                    ulonglong2 w1 = *(const ulonglong2*)(wp + o1);
                    ulonglong2 w2 = *(const ulonglong2*)(wp + o2);
                    ulonglong2 w3 = *(const ulonglong2*)(wp + o3);
                    FMA2(c0, w0.x, gsd.x, c0); FMA2(s0, w0.y, gsd.y, s0);
                    FMA2(c1, w1.x, gsd.x, c1); FMA2(s1, w1.y, gsd.y, s1);
                    FMA2(c2, w2.x, gsd.x, c2); FMA2(s2, w2.y, gsd.y, s2);
                    FMA2(c3, w3.x, gsd.x, c3); FMA2(s3, w3.y, gsd.y, s3);
                    o0 += s0i; o1 += s1i; o2 += s2i; o3 += s3i;
                }
                {
                    ulonglong2 gsd = *(const ulonglong2*)gp;
                    gp += GSTRIDE * 16;
                    ulonglong2 w0 = *(const ulonglong2*)(wp + o0);
                    ulonglong2 w1 = *(const ulonglong2*)(wp + o1);
                    ulonglong2 w2 = *(const ulonglong2*)(wp + o2);
                    ulonglong2 w3 = *(const ulonglong2*)(wp + o3);
                    FMA2(c0, w0.x, gsd.x, c0); FMA2(s0, w0.y, gsd.y, s0);
                    FMA2(c1, w1.x, gsd.x, c1); FMA2(s1, w1.y, gsd.y, s1);
                    FMA2(c2, w2.x, gsd.x, c2); FMA2(s2, w2.y, gsd.y, s2);
                    FMA2(c3, w3.x, gsd.x, c3); FMA2(s3, w3.y, gsd.y, s3);
                    o0 = (o0 + s0i) & 4095; o1 = (o1 + s1i) & 4095;
                    o2 = (o2 + s2i) & 4095; o3 = (o3 + s3i) & 4095;
                }
            }

            float2 g0 = G0[v];
            int tcol = (v + 32) & 255;

            #pragma unroll
            for (int j = 0; j < 4; j++) {
                ull cj = (j == 0) ? c0 : (j == 1) ? c1 : (j == 2) ? c2 : c3;
                ull sj = (j == 0) ? s0 : (j == 1) ? s1 : (j == 2) ? s2 : s3;
                float2 ac = u2f2(cj);
                float2 as = u2f2(sj);
                float t1r = g0.x + ac.x, t1i = g0.y + ac.y;
                float orx = t1r - as.x, oix = t1i + as.y;   // out(u)
                float prx = t1r + as.x, pix = t1i - as.y;   // out(256-u)
                float p2a = fmaf(orx, orx, oix * oix);
                float p2b = fmaf(prx, prx, pix * pix);
                lmax = fmaxf(lmax, fmaxf(p2a, p2b));
                int u  = u0 + j;
                int sa = (u + 32) & 255;
                if (sa < 64) crop[(sa << 6) + tcol] = p2a;
                int sb = (32 - u) & 255;
                if (sb < 64) crop[(sb << 6) + tcol] = p2b;
            }
        } else {
            // ---- window unit (tile 8): max-only, 80u x 96v at (iu, iv) ----
            int t2  = t - 18;                // 0..29
            int wvb = t2 / 10;               // 0..2
            int wt  = t2 - wvb * 10;         // 0..9
            int vbase = (wv0 + (wvb << 5)) & 255;
            int vidx  = vbase + lane;        // padded index <= 286
            int ub    = wu0 + (wt << 3);

            int st0 = (((ub + 0) & 255) << 4), st1 = (((ub + 1) & 255) << 4);
            int st2 = (((ub + 2) & 255) << 4), st3 = (((ub + 3) & 255) << 4);
            int st4 = (((ub + 4) & 255) << 4), st5 = (((ub + 5) & 255) << 4);
            int st6 = (((ub + 6) & 255) << 4), st7 = (((ub + 7) & 255) << 4);
            int o0 = st0, o1 = st1, o2 = st2, o3 = st3;
            int o4 = st4, o5 = st5, o6 = st6, o7 = st7;
            ull c0 = 0, s0 = 0, c1 = 0, s1 = 0;
            ull c2 = 0, s2 = 0, c3 = 0, s3 = 0;
            ull c4 = 0, s4 = 0, c5 = 0, s5 = 0;
            ull c6 = 0, s6 = 0, c7 = 0, s7 = 0;

            const char* gp = (const char*)(SGDG + vidx);
            #pragma unroll 3
            for (int mh = 0; mh < 12; mh++) {
                {
                    ulonglong2 gsd = *(const ulonglong2*)gp;
                    gp += GSTRIDE * 16;
                    ulonglong2 w0 = *(const ulonglong2*)(wp + o0);
                    ulonglong2 w1 = *(const ulonglong2*)(wp + o1);
                    ulonglong2 w2 = *(const ulonglong2*)(wp + o2);
                    ulonglong2 w3 = *(const ulonglong2*)(wp + o3);
                    FMA2(c0, w0.x, gsd.x, c0); FMA2(s0, w0.y, gsd.y, s0);
                    FMA2(c1, w1.x, gsd.x, c1); FMA2(s1, w1.y, gsd.y, s1);
                    FMA2(c2, w2.x, gsd.x, c2); FMA2(s2, w2.y, gsd.y, s2);
                    FMA2(c3, w3.x, gsd.x, c3); FMA2(s3, w3.y, gsd.y, s3);
                    ulonglong2 w4 = *(const ulonglong2*)(wp + o4);
                    ulonglong2 w5 = *(const ulonglong2*)(wp + o5);
                    ulonglong2 w6 = *(const ulonglong2*)(wp + o6);
                    ulonglong2 w7 = *(const ulonglong2*)(wp + o7);
                    FMA2(c4, w4.x, gsd.x, c4); FMA2(s4, w4.y, gsd.y, s4);
                    FMA2(c5, w5.x, gsd.x, c5); FMA2(s5, w5.y, gsd.y, s5);
                    FMA2(c6, w6.x, gsd.x, c6); FMA2(s6, w6.y, gsd.y, s6);
                    FMA2(c7, w7.x, gsd.x, c7); FMA2(s7, w7.y, gsd.y, s7);
                    o0 += st0; o1 += st1; o2 += st2; o3 += st3;
                    o4 += st4; o5 += st5; o6 += st6; o7 += st7;
                }
                {
                    ulonglong2 gsd = *(const ulonglong2*)gp;
                    gp += GSTRIDE * 16;
                    ulonglong2 w0 = *(const ulonglong2*)(wp + o0);
                    ulonglong2 w1 = *(const ulonglong2*)(wp + o1);
                    ulonglong2 w2 = *(const ulonglong2*)(wp + o2);
                    ulonglong2 w3 = *(const ulonglong2*)(wp + o3);
                    FMA2(c0, w0.x, gsd.x, c0); FMA2(s0, w0.y, gsd.y, s0);
                    FMA2(c1, w1.x, gsd.x, c1); FMA2(s1, w1.y, gsd.y, s1);
                    FMA2(c2, w2.x, gsd.x, c2); FMA2(s2, w2.y, gsd.y, s2);
                    FMA2(c3, w3.x, gsd.x, c3); FMA2(s3, w3.y, gsd.y, s3);
                    ulonglong2 w4 = *(const ulonglong2*)(wp + o4);
                    ulonglong2 w5 = *(const ulonglong2*)(wp + o5);
                    ulonglong2 w6 = *(const ulonglong2*)(wp + o6);
                    ulonglong2 w7 = *(const ulonglong2*)(wp + o7);
                    FMA2(c4, w4.x, gsd.x, c4); FMA2(s4, w4.y, gsd.y, s4);
                    FMA2(c5, w5.x, gsd.x, c5); FMA2(s5, w5.y, gsd.y, s5);
                    FMA2(c6, w6.x, gsd.x, c6); FMA2(s6, w6.y, gsd.y, s6);
                    FMA2(c7, w7.x, gsd.x, c7); FMA2(s7, w7.y, gsd.y, s7);
                    o0 = (o0 + st0) & 4095; o1 = (o1 + st1) & 4095;
                    o2 = (o2 + st2) & 4095; o3 = (o3 + st3) & 4095;
                    o4 = (o4 + st4) & 4095; o5 = (o5 + st5) & 4095;
                    o6 = (o6 + st6) & 4095; o7 = (o7 + st7) & 4095;
                }
            }

            float2 g0 = G0[vidx];
            float gr = g0.x, gi = g0.y;
            #pragma unroll
            for (int j = 0; j < 8; j++) {
                ull cj, sj;
                switch (j) {
                    case 0: cj = c0; sj = s0; break;
                    case 1: cj = c1; sj = s1; break;
                    case 2: cj = c2; sj = s2; break;
                    case 3: cj = c3; sj = s3; break;
                    case 4: cj = c4; sj = s4; break;
                    case 5: cj = c5; sj = s5; break;
                    case 6: cj = c6; sj = s6; break;
                    default: cj = c7; sj = s7; break;
                }
                float2 ac = u2f2(cj);
                float2 as = u2f2(sj);
                float orx = gr + ac.x - as.x;
                float oix = gi + ac.y + as.y;
                lmax = fmaxf(lmax, fmaf(orx, orx, oix * oix));
            }
        }
    }

    // ---- CTA max reduction ----
    #pragma unroll
    for (int o = 16; o > 0; o >>= 1)
        lmax = fmaxf(lmax, __shfl_xor_sync(0xFFFFFFFFu, lmax, o));
    if (lane == 0) red[warp] = lmax;
    __syncthreads();
    if (warp == 0) {
        float m = red[lane];
        #pragma unroll
        for (int o = 16; o > 0; o >>= 1)
            m = fmaxf(m, __shfl_xor_sync(0xFFFFFFFFu, m, o));
        if (lane == 0) red[0] = m;
    }
    __syncthreads();
    const float maxv = red[0];

    // ---- epilogue: atomic-accumulate (psf/max * A + bg) * mask into out[b] ----
    const float A    = Aa[img];
    const float bg   = Bg[img];
    const float mask = (P[img] > 0.5f) ? 1.0f : 0.0f;
    const float scale = (A / maxv) * mask;
    const float bgm   = bg * mask;
    float* outb = out + (size_t)(img >> 2) * 4096;
    #pragma unroll
    for (int k = 0; k < 4; k++) {
        int idx = tid + k * NTHREADS;
        atomicAdd(&outb[idx], fmaf(crop[idx], scale, bgm));
    }
}

extern "C" void kernel_launch(void* const* d_in, const int* in_sizes, int n_in,
                              void* d_out, int out_size)
{
    (void)in_sizes; (void)n_in;
    cudaMemsetAsync(d_out, 0, (size_t)out_size * sizeof(float));
    cudaFuncSetAttribute(render_kernel,
                         cudaFuncAttributeMaxDynamicSharedMemorySize, SM_TOTAL);
    render_kernel<<<NIMG, NTHREADS, SM_TOTAL>>>(
        (const float*)d_in[0], (const float*)d_in[1], (const float*)d_in[2],
        (const float*)d_in[3], (const float*)d_in[4], (const float*)d_in[5],
        (const float*)d_in[6], (float*)d_out);
}

// round 9
// speedup vs baseline: 1.3707x; 1.3707x over previous
#include <cuda_runtime.h>
#include <math.h>

#define NIMG 256        // B*N = 64*4
#define NTHREADS 1024

typedef unsigned long long ull;

// ---- dynamic shared layout (bytes) ----
#define SM_CSB  0                    // float2 [49] base col   = 512 (padded)
#define SM_SDB  (SM_CSB + 512)       // float4 [49][24]        = 18816
#define SM_WT   (SM_SDB + 18816)     // float2 [256]           = 2048
#define SM_WP   (SM_WT + 2048)       // ulonglong2 [256]       = 4096
#define SM_SGDG (SM_WP + 4096)       // float4 [24][288]       = 110592
#define SM_G0   (SM_SGDG + 110592)   // float2 [288]           = 2304
#define SM_CROP (SM_G0 + 2304)       // float  [4096]          = 16384
#define SM_RED  (SM_CROP + 16384)    // float  [32]            = 128
#define SM_TOTAL (SM_RED + 128)      // 154880 bytes

#define GSTRIDE 288

extern __shared__ char smem_raw[];

#define FMA2(d, a, b, c) \
    asm("fma.rn.f32x2 %0, %1, %2, %3;" : "=l"(d) : "l"(a), "l"(b), "l"(c))

__device__ __forceinline__ float2 u2f2(ull v) {
    float2 r;
    asm("mov.b64 {%0, %1}, %2;" : "=f"(r.x), "=f"(r.y) : "l"(v));
    return r;
}
__device__ __forceinline__ ull splat2(float f) {
    ull r;
    asm("mov.b64 %0, {%1, %1};" : "=l"(r) : "f"(f));
    return r;
}

__device__ __forceinline__ float2 pupil_pt(int a, int b, float x, float y,
                                           float z, const float* __restrict__ ph)
{
    float us = (float)(2 * a - 63) * (1.0f / 47.25f);
    float vs = (float)(2 * b - 63) * (1.0f / 47.25f);
    float R  = sqrtf(us * us + vs * vs);
    if (R > 1.0f) return make_float2(0.0f, 0.0f);
    float prop = sqrtf(fmaxf(1.0f - R * R, 0.0f));
    float psi = ph[a * 64 + b] + prop * z
              - (6.283185307179586f / 256.0f)
                * ((float)(a - 32) * x + (float)(b - 32) * y);
    float sn, cs;
    __sincosf(psi, &sn, &cs);
    return make_float2(cs, sn);
}

__global__ void __launch_bounds__(NTHREADS, 1)
render_kernel(const float* __restrict__ X,  const float* __restrict__ Y,
              const float* __restrict__ Z,  const float* __restrict__ Aa,
              const float* __restrict__ Bg, const float* __restrict__ P,
              const float* __restrict__ phase0,
              float* __restrict__ out)
{
    float2*     CsB  = (float2*)    (smem_raw + SM_CSB);
    float4*     SDB  = (float4*)    (smem_raw + SM_SDB);
    float2*     Wt   = (float2*)    (smem_raw + SM_WT);
    ulonglong2* Wp   = (ulonglong2*)(smem_raw + SM_WP);
    float4*     SGDG = (float4*)    (smem_raw + SM_SGDG);
    float2*     G0   = (float2*)    (smem_raw + SM_G0);
    float*      crop = (float*)     (smem_raw + SM_CROP);
    float*      red  = (float*)     (smem_raw + SM_RED);

    const int img  = blockIdx.x;
    const int tid  = threadIdx.x;
    const int lane = tid & 31;
    const int warp = tid >> 5;     // 0..31

    const float x = X[img], y = Y[img], z = Z[img];

    // ---- twiddle tables: W[k] = exp(2*pi*i*k/256) ----
    if (tid < 256) {
        float s, c;
        sincospif((float)tid * (1.0f / 128.0f), &s, &c);
        Wt[tid] = make_float2(c, s);
        Wp[tid] = make_ulonglong2(splat2(c), splat2(s));
    }

    // ---- fused Phase A + SDB: thread per (row r, fold q) pair ----
    // SDB[r][q-1] = (S.r, S.i, D.i, D.r) with S/D = C[a][32+q] +/- C[a][32-q]
    for (int idx = tid; idx < 49 * 25; idx += NTHREADS) {
        int r = idx / 25;
        int q = idx - r * 25;               // 0..24
        int a = r + 8;
        if (q == 0) {
            CsB[r] = pupil_pt(a, 32, x, y, z, phase0);
        } else {
            float2 cu = pupil_pt(a, 32 + q, x, y, z, phase0);
            float2 cd = pupil_pt(a, 32 - q, x, y, z, phase0);
            SDB[r * 24 + (q - 1)] = make_float4(cu.x + cd.x, cu.y + cd.y,
                                                cu.y - cd.y, cu.x - cd.x);
        }
    }
    __syncthreads();

    // ---- Phase B (packed f32x2): row-paired, v-folded column DFT ----
    // elliptical trip bound: columns beyond pupil disk are exactly zero
    for (int i = 0; i < 4; i++) {
        int t = warp + 32 * i;
        if (t >= 100) break;
        int m  = t >> 2;
        int vb = t & 3;
        int v  = (vb << 5) + lane;          // 0..127

        int mm = 2 * m - 1;
        float wrad = 2232.5625f - (float)(mm * mm);
        int qe = min(24, (int)((sqrtf(wrad) - 1.0f) * 0.5f) + 2);

        float2 w0 = Wt[v];
        ull CC  = splat2(w0.x), SS  = splat2(w0.y);
        ull RC  = CC,           RS  = SS;
        ull NRS = splat2(-w0.y);
        const ull ZERO = 0;

        ull ACu = 0, ASu = 0, ACd = 0, ASd = 0;
        const ulonglong2* sup = (const ulonglong2*)(SDB + (24 + m) * 24);
        const ulonglong2* sdn = (const ulonglong2*)(SDB + (24 - m) * 24);

        if (m == 0) {
            #pragma unroll 4
            for (int mb = 0; mb < qe; mb++) {
                ulonglong2 sv = sup[mb];
                FMA2(ACu, CC, sv.x, ACu);
                FMA2(ASu, SS, sv.y, ASu);
                ull t1, t2;
                FMA2(t1, CC, RC, ZERO); FMA2(t2, CC, RS, ZERO);
                FMA2(CC, SS, NRS, t1);  FMA2(SS, SS, RC, t2);
            }
            float2 ac = u2f2(ACu), as = u2f2(ASu);
            float2 base = CsB[24];
            float2 glo = make_float2(base.x + ac.x - as.x, base.y + ac.y + as.y);
            float2 ghi = make_float2(base.x + ac.x + as.x, base.y + ac.y - as.y);
            G0[v] = glo;
            G0[(256 - v) & 255] = ghi;
            if (v < 32) G0[256 + v] = (v == 0) ? ghi : glo;
        } else {
            #pragma unroll 4
            for (int mb = 0; mb < qe; mb++) {
                ulonglong2 sv = sup[mb];
                ulonglong2 dv = sdn[mb];
                FMA2(ACu, CC, sv.x, ACu);
                FMA2(ASu, SS, sv.y, ASu);
                FMA2(ACd, CC, dv.x, ACd);
                FMA2(ASd, SS, dv.y, ASd);
                ull t1, t2;
                FMA2(t1, CC, RC, ZERO); FMA2(t2, CC, RS, ZERO);
                FMA2(CC, SS, NRS, t1);  FMA2(SS, SS, RC, t2);
            }
            float2 acu = u2f2(ACu), asu = u2f2(ASu);
            float2 acd = u2f2(ACd), asd = u2f2(ASd);
            float2 bu = CsB[24 + m];
            float2 bd = CsB[24 - m];
            float2 up_lo = make_float2(bu.x + acu.x - asu.x, bu.y + acu.y + asu.y);
            float2 up_hi = make_float2(bu.x + acu.x + asu.x, bu.y + acu.y - asu.y);
            float2 dn_lo = make_float2(bd.x + acd.x - asd.x, bd.y + acd.y + asd.y);
            float2 dn_hi = make_float2(bd.x + acd.x + asd.x, bd.y + acd.y - asd.y);
            int base = (m - 1) * GSTRIDE;
            int vh = (256 - v) & 255;
            float4 lo4 = make_float4(up_lo.x + dn_lo.x, up_lo.y + dn_lo.y,
                                     up_lo.y - dn_lo.y, up_lo.x - dn_lo.x);
            float4 hi4 = make_float4(up_hi.x + dn_hi.x, up_hi.y + dn_hi.y,
                                     up_hi.y - dn_hi.y, up_hi.x - dn_hi.x);
            SGDG[base + v]  = lo4;
            SGDG[base + vh] = hi4;
            if (v < 32) SGDG[base + 256 + v] = (v == 0) ? hi4 : lo4;
        }
    }

    // ---- v = 128 column (sin = 0, cos = (-1)^q) ----
    if (tid >= 896 && tid < 921) {
        int m = tid - 896;                  // 0..24
        int mm = 2 * m - 1;
        float wrad = 2232.5625f - (float)(mm * mm);
        int qe = min(24, (int)((sqrtf(wrad) - 1.0f) * 0.5f) + 2);
        float2 up = CsB[24 + m];
        float2 dn = CsB[24 - m];
        const float4* sup = SDB + (24 + m) * 24;
        const float4* sdn = SDB + (24 - m) * 24;
        float sgn = -1.f;
        #pragma unroll 4
        for (int mb = 0; mb < qe; mb++) {
            float4 su = sup[mb]; float4 sd = sdn[mb];
            up.x = fmaf(sgn, su.x, up.x); up.y = fmaf(sgn, su.y, up.y);
            dn.x = fmaf(sgn, sd.x, dn.x); dn.y = fmaf(sgn, sd.y, dn.y);
            sgn = -sgn;
        }
        if (m == 0) {
            G0[128] = up;
        } else {
            SGDG[(m - 1) * GSTRIDE + 128] =
                make_float4(up.x + dn.x, up.y + dn.y,
                            up.y - dn.y, up.x - dn.x);
        }
    }
    __syncthreads();

    // ---- Phase C: crop (u-folded, 18 units, tile 4)
    //              + 80u x 96v max-window (30 units, tile 8) ----
    const int iu = (int)(((unsigned)__float2int_rn(x)) & 255u);
    const int iv = (int)(((unsigned)__float2int_rn(y)) & 255u);
    const int wu0 = (iu - 40) & 255;
    const int wv0 = (iv - 48) & 255;

    float lmax = 0.0f;
    const char* wp = (const char*)Wp;

    for (int i = 0; i < 2; i++) {
        int t = warp + 32 * i;
        if (t >= 48) break;

        if (t < 18) {
            // ---- crop unit: ut 0..8 -> u0 = 4*ut; vb 0..1 ----
            int ut = t >> 1;
            int vb = t & 1;
            int v  = vb ? (224 + lane) : lane;
            int u0 = ut << 2;

            int o0 = ((u0 + 0) << 4) & 4095, o1 = ((u0 + 1) << 4) & 4095;
            int o2 = ((u0 + 2) << 4) & 4095, o3 = ((u0 + 3) << 4) & 4095;
            ull c0 = 0, s0 = 0, c1 = 0, s1 = 0;
            ull c2 = 0, s2 = 0, c3 = 0, s3 = 0;

            const char* gp = (const char*)(SGDG + v);
            #pragma unroll 4
            for (int m = 1; m <= 24; m++) {
                ulonglong2 gsd = *(const ulonglong2*)gp;
                gp += GSTRIDE * 16;
                ulonglong2 w0 = *(const ulonglong2*)(wp + o0);
                ulonglong2 w1 = *(const ulonglong2*)(wp + o1);
                ulonglong2 w2 = *(const ulonglong2*)(wp + o2);
                ulonglong2 w3 = *(const ulonglong2*)(wp + o3);
                FMA2(c0, w0.x, gsd.x, c0); FMA2(s0, w0.y, gsd.y, s0);
                FMA2(c1, w1.x, gsd.x, c1); FMA2(s1, w1.y, gsd.y, s1);
                FMA2(c2, w2.x, gsd.x, c2); FMA2(s2, w2.y, gsd.y, s2);
                FMA2(c3, w3.x, gsd.x, c3); FMA2(s3, w3.y, gsd.y, s3);
                o0 = (o0 + ((u0 + 0) << 4)) & 4095;
                o1 = (o1 + ((u0 + 1) << 4)) & 4095;
                o2 = (o2 + ((u0 + 2) << 4)) & 4095;
                o3 = (o3 + ((u0 + 3) << 4)) & 4095;
            }

            float2 g0 = G0[v];
            int tcol = (v + 32) & 255;

            #pragma unroll
            for (int j = 0; j < 4; j++) {
                ull cj = (j == 0) ? c0 : (j == 1) ? c1 : (j == 2) ? c2 : c3;
                ull sj = (j == 0) ? s0 : (j == 1) ? s1 : (j == 2) ? s2 : s3;
                float2 ac = u2f2(cj);
                float2 as = u2f2(sj);
                float t1r = g0.x + ac.x, t1i = g0.y + ac.y;
                float orx = t1r - as.x, oix = t1i + as.y;   // out(u)
                float prx = t1r + as.x, pix = t1i - as.y;   // out(256-u)
                float p2a = fmaf(orx, orx, oix * oix);
                float p2b = fmaf(prx, prx, pix * pix);
                lmax = fmaxf(lmax, fmaxf(p2a, p2b));
                int u  = u0 + j;
                int sa = (u + 32) & 255;
                if (sa < 64) crop[(sa << 6) + tcol] = p2a;
                int sb = (32 - u) & 255;
                if (sb < 64) crop[(sb << 6) + tcol] = p2b;
            }
        } else {
            // ---- window unit (tile 8): max-only, 80u x 96v at (iu, iv) ----
            int t2  = t - 18;                // 0..29
            int wvb = t2 / 10;               // 0..2
            int wt  = t2 - wvb * 10;         // 0..9
            int vbase = (wv0 + (wvb << 5)) & 255;
            int vidx  = vbase + lane;        // padded index <= 286
            int ub    = wu0 + (wt << 3);

            int st0 = (((ub + 0) & 255) << 4), st1 = (((ub + 1) & 255) << 4);
            int st2 = (((ub + 2) & 255) << 4), st3 = (((ub + 3) & 255) << 4);
            int st4 = (((ub + 4) & 255) << 4), st5 = (((ub + 5) & 255) << 4);
            int st6 = (((ub + 6) & 255) << 4), st7 = (((ub + 7) & 255) << 4);
            int o0 = st0, o1 = st1, o2 = st2, o3 = st3;
            int o4 = st4, o5 = st5, o6 = st6, o7 = st7;
            ull c0 = 0, s0 = 0, c1 = 0, s1 = 0;
            ull c2 = 0, s2 = 0, c3 = 0, s3 = 0;
            ull c4 = 0, s4 = 0, c5 = 0, s5 = 0;
            ull c6 = 0, s6 = 0, c7 = 0, s7 = 0;

            const char* gp = (const char*)(SGDG + vidx);
            #pragma unroll 4
            for (int m = 1; m <= 24; m++) {
                ulonglong2 gsd = *(const ulonglong2*)gp;
                gp += GSTRIDE * 16;
                ulonglong2 w0 = *(const ulonglong2*)(wp + o0);
                ulonglong2 w1 = *(const ulonglong2*)(wp + o1);
                ulonglong2 w2 = *(const ulonglong2*)(wp + o2);
                ulonglong2 w3 = *(const ulonglong2*)(wp + o3);
                FMA2(c0, w0.x, gsd.x, c0); FMA2(s0, w0.y, gsd.y, s0);
                FMA2(c1, w1.x, gsd.x, c1); FMA2(s1, w1.y, gsd.y, s1);
                FMA2(c2, w2.x, gsd.x, c2); FMA2(s2, w2.y, gsd.y, s2);
                FMA2(c3, w3.x, gsd.x, c3); FMA2(s3, w3.y, gsd.y, s3);
                o0 = (o0 + st0) & 4095;
                o1 = (o1 + st1) & 4095;
                o2 = (o2 + st2) & 4095;
                o3 = (o3 + st3) & 4095;
                ulonglong2 w4 = *(const ulonglong2*)(wp + o4);
                ulonglong2 w5 = *(const ulonglong2*)(wp + o5);
                ulonglong2 w6 = *(const ulonglong2*)(wp + o6);
                ulonglong2 w7 = *(const ulonglong2*)(wp + o7);
                FMA2(c4, w4.x, gsd.x, c4); FMA2(s4, w4.y, gsd.y, s4);
                FMA2(c5, w5.x, gsd.x, c5); FMA2(s5, w5.y, gsd.y, s5);
                FMA2(c6, w6.x, gsd.x, c6); FMA2(s6, w6.y, gsd.y, s6);
                FMA2(c7, w7.x, gsd.x, c7); FMA2(s7, w7.y, gsd.y, s7);
                o4 = (o4 + st4) & 4095;
                o5 = (o5 + st5) & 4095;
                o6 = (o6 + st6) & 4095;
                o7 = (o7 + st7) & 4095;
            }

            float2 g0 = G0[vidx];
            float gr = g0.x, gi = g0.y;
            #pragma unroll
            for (int j = 0; j < 8; j++) {
                ull cj, sj;
                switch (j) {
                    case 0: cj = c0; sj = s0; break;
                    case 1: cj = c1; sj = s1; break;
                    case 2: cj = c2; sj = s2; break;
                    case 3: cj = c3; sj = s3; break;
                    case 4: cj = c4; sj = s4; break;
                    case 5: cj = c5; sj = s5; break;
                    case 6: cj = c6; sj = s6; break;
                    default: cj = c7; sj = s7; break;
                }
                float2 ac = u2f2(cj);
                float2 as = u2f2(sj);
                float orx = gr + ac.x - as.x;
                float oix = gi + ac.y + as.y;
                lmax = fmaxf(lmax, fmaf(orx, orx, oix * oix));
            }
        }
    }

    // ---- CTA max reduction ----
    #pragma unroll
    for (int o = 16; o > 0; o >>= 1)
        lmax = fmaxf(lmax, __shfl_xor_sync(0xFFFFFFFFu, lmax, o));
    if (lane == 0) red[warp] = lmax;
    __syncthreads();
    if (warp == 0) {
        float m = red[lane];
        #pragma unroll
        for (int o = 16; o > 0; o >>= 1)
            m = fmaxf(m, __shfl_xor_sync(0xFFFFFFFFu, m, o));
        if (lane == 0) red[0] = m;
    }
    __syncthreads();
    const float maxv = red[0];

    // ---- epilogue: atomic-accumulate (psf/max * A + bg) * mask into out[b] ----
    const float A    = Aa[img];
    const float bg   = Bg[img];
    const float mask = (P[img] > 0.5f) ? 1.0f : 0.0f;
    const float scale = (A / maxv) * mask;
    const float bgm   = bg * mask;
    float* outb = out + (size_t)(img >> 2) * 4096;
    #pragma unroll
    for (int k = 0; k < 4; k++) {
        int idx = tid + k * NTHREADS;
        atomicAdd(&outb[idx], fmaf(crop[idx], scale, bgm));
    }
}

extern "C" void kernel_launch(void* const* d_in, const int* in_sizes, int n_in,
                              void* d_out, int out_size)
{
    (void)in_sizes; (void)n_in;
    cudaMemsetAsync(d_out, 0, (size_t)out_size * sizeof(float));
    cudaFuncSetAttribute(render_kernel,
                         cudaFuncAttributeMaxDynamicSharedMemorySize, SM_TOTAL);
    render_kernel<<<NIMG, NTHREADS, SM_TOTAL>>>(
        (const float*)d_in[0], (const float*)d_in[1], (const float*)d_in[2],
        (const float*)d_in[3], (const float*)d_in[4], (const float*)d_in[5],
        (const float*)d_in[6], (float*)d_out);
}

// round 10
// speedup vs baseline: 1.4930x; 1.0892x over previous
#include <cuda_runtime.h>
#include <math.h>

#define NIMG 256        // B*N = 64*4
#define NTHREADS 1024

typedef unsigned long long ull;

// ---- dynamic shared layout (bytes) ----
#define SM_CSB  0                    // float2 [49] base col   = 512 (padded)
#define SM_SDB  (SM_CSB + 512)       // float4 [49][24]        = 18816
#define SM_WT   (SM_SDB + 18816)     // float2 [256]           = 2048
#define SM_WP   (SM_WT + 2048)       // ulonglong2 [256]       = 4096
#define SM_SGDG (SM_WP + 4096)       // float4 [24][288]       = 110592
#define SM_G0   (SM_SGDG + 110592)   // float2 [288]           = 2304
#define SM_CROP (SM_G0 + 2304)       // float  [4096]          = 16384
#define SM_RED  (SM_CROP + 16384)    // float  [32]            = 128
#define SM_TOTAL (SM_RED + 128)      // 154880 bytes

#define GSTRIDE 288

extern __shared__ char smem_raw[];

#define FMA2(d, a, b, c) \
    asm("fma.rn.f32x2 %0, %1, %2, %3;" : "=l"(d) : "l"(a), "l"(b), "l"(c))

__device__ __forceinline__ float2 u2f2(ull v) {
    float2 r;
    asm("mov.b64 {%0, %1}, %2;" : "=f"(r.x), "=f"(r.y) : "l"(v));
    return r;
}
__device__ __forceinline__ ull splat2(float f) {
    ull r;
    asm("mov.b64 %0, {%1, %1};" : "=l"(r) : "f"(f));
    return r;
}

__device__ __forceinline__ float2 pupil_pt(int a, int b, float x, float y,
                                           float z, const float* __restrict__ ph)
{
    float us = (float)(2 * a - 63) * (1.0f / 47.25f);
    float vs = (float)(2 * b - 63) * (1.0f / 47.25f);
    float R  = sqrtf(us * us + vs * vs);
    if (R > 1.0f) return make_float2(0.0f, 0.0f);
    float prop = sqrtf(fmaxf(1.0f - R * R, 0.0f));
    float psi = ph[a * 64 + b] + prop * z
              - (6.283185307179586f / 256.0f)
                * ((float)(a - 32) * x + (float)(b - 32) * y);
    float sn, cs;
    __sincosf(psi, &sn, &cs);
    return make_float2(cs, sn);
}

__global__ void __launch_bounds__(NTHREADS, 1)
render_kernel(const float* __restrict__ X,  const float* __restrict__ Y,
              const float* __restrict__ Z,  const float* __restrict__ Aa,
              const float* __restrict__ Bg, const float* __restrict__ P,
              const float* __restrict__ phase0,
              float* __restrict__ out)
{
    float2*     CsB  = (float2*)    (smem_raw + SM_CSB);
    float4*     SDB  = (float4*)    (smem_raw + SM_SDB);
    float2*     Wt   = (float2*)    (smem_raw + SM_WT);
    ulonglong2* Wp   = (ulonglong2*)(smem_raw + SM_WP);
    float4*     SGDG = (float4*)    (smem_raw + SM_SGDG);
    float2*     G0   = (float2*)    (smem_raw + SM_G0);
    float*      crop = (float*)     (smem_raw + SM_CROP);
    float*      red  = (float*)     (smem_raw + SM_RED);

    const int img  = blockIdx.x;
    const int tid  = threadIdx.x;
    const int lane = tid & 31;
    const int warp = tid >> 5;     // 0..31

    const float x = X[img], y = Y[img], z = Z[img];

    // ---- twiddle tables: W[k] = exp(2*pi*i*k/256) ----
    if (tid < 256) {
        float s, c;
        sincospif((float)tid * (1.0f / 128.0f), &s, &c);
        Wt[tid] = make_float2(c, s);
        Wp[tid] = make_ulonglong2(splat2(c), splat2(s));
    }

    // ---- fused Phase A + SDB: thread per (row r, fold q) pair ----
    // SDB[r][q-1] = (S.r, S.i, D.i, D.r) with S/D = C[a][32+q] +/- C[a][32-q]
    for (int idx = tid; idx < 49 * 25; idx += NTHREADS) {
        int r = idx / 25;
        int q = idx - r * 25;               // 0..24
        int a = r + 8;
        if (q == 0) {
            CsB[r] = pupil_pt(a, 32, x, y, z, phase0);
        } else {
            float2 cu = pupil_pt(a, 32 + q, x, y, z, phase0);
            float2 cd = pupil_pt(a, 32 - q, x, y, z, phase0);
            SDB[r * 24 + (q - 1)] = make_float4(cu.x + cd.x, cu.y + cd.y,
                                                cu.y - cd.y, cu.x - cd.x);
        }
    }
    __syncthreads();

    // ---- Phase B (packed f32x2): row-paired, v-folded column DFT ----
    // elliptical trip bound: columns beyond pupil disk are exactly zero
    for (int i = 0; i < 4; i++) {
        int t = warp + 32 * i;
        if (t >= 100) break;
        int m  = t >> 2;
        int vb = t & 3;
        int v  = (vb << 5) + lane;          // 0..127

        int mm = 2 * m - 1;
        float wrad = 2232.5625f - (float)(mm * mm);
        int qe = min(24, (int)((sqrtf(wrad) - 1.0f) * 0.5f) + 2);

        float2 w0 = Wt[v];
        ull CC  = splat2(w0.x), SS  = splat2(w0.y);
        ull RC  = CC,           RS  = SS;
        ull NRS = splat2(-w0.y);
        const ull ZERO = 0;

        ull ACu = 0, ASu = 0, ACd = 0, ASd = 0;
        const ulonglong2* sup = (const ulonglong2*)(SDB + (24 + m) * 24);
        const ulonglong2* sdn = (const ulonglong2*)(SDB + (24 - m) * 24);

        if (m == 0) {
            #pragma unroll 4
            for (int mb = 0; mb < qe; mb++) {
                ulonglong2 sv = sup[mb];
                FMA2(ACu, CC, sv.x, ACu);
                FMA2(ASu, SS, sv.y, ASu);
                ull t1, t2;
                FMA2(t1, CC, RC, ZERO); FMA2(t2, CC, RS, ZERO);
                FMA2(CC, SS, NRS, t1);  FMA2(SS, SS, RC, t2);
            }
            float2 ac = u2f2(ACu), as = u2f2(ASu);
            float2 base = CsB[24];
            float2 glo = make_float2(base.x + ac.x - as.x, base.y + ac.y + as.y);
            float2 ghi = make_float2(base.x + ac.x + as.x, base.y + ac.y - as.y);
            G0[v] = glo;
            G0[(256 - v) & 255] = ghi;
            if (v < 32) G0[256 + v] = (v == 0) ? ghi : glo;
        } else {
            #pragma unroll 4
            for (int mb = 0; mb < qe; mb++) {
                ulonglong2 sv = sup[mb];
                ulonglong2 dv = sdn[mb];
                FMA2(ACu, CC, sv.x, ACu);
                FMA2(ASu, SS, sv.y, ASu);
                FMA2(ACd, CC, dv.x, ACd);
                FMA2(ASd, SS, dv.y, ASd);
                ull t1, t2;
                FMA2(t1, CC, RC, ZERO); FMA2(t2, CC, RS, ZERO);
                FMA2(CC, SS, NRS, t1);  FMA2(SS, SS, RC, t2);
            }
            float2 acu = u2f2(ACu), asu = u2f2(ASu);
            float2 acd = u2f2(ACd), asd = u2f2(ASd);
            float2 bu = CsB[24 + m];
            float2 bd = CsB[24 - m];
            float2 up_lo = make_float2(bu.x + acu.x - asu.x, bu.y + acu.y + asu.y);
            float2 up_hi = make_float2(bu.x + acu.x + asu.x, bu.y + acu.y - asu.y);
            float2 dn_lo = make_float2(bd.x + acd.x - asd.x, bd.y + acd.y + asd.y);
            float2 dn_hi = make_float2(bd.x + acd.x + asd.x, bd.y + acd.y - asd.y);
            int base = (m - 1) * GSTRIDE;
            int vh = (256 - v) & 255;
            float4 lo4 = make_float4(up_lo.x + dn_lo.x, up_lo.y + dn_lo.y,
                                     up_lo.y - dn_lo.y, up_lo.x - dn_lo.x);
            float4 hi4 = make_float4(up_hi.x + dn_hi.x, up_hi.y + dn_hi.y,
                                     up_hi.y - dn_hi.y, up_hi.x - dn_hi.x);
            SGDG[base + v]  = lo4;
            SGDG[base + vh] = hi4;
            if (v < 32) SGDG[base + 256 + v] = (v == 0) ? hi4 : lo4;
        }
    }

    // ---- v = 128 column (sin = 0, cos = (-1)^q) ----
    if (tid >= 896 && tid < 921) {
        int m = tid - 896;                  // 0..24
        int mm = 2 * m - 1;
        float wrad = 2232.5625f - (float)(mm * mm);
        int qe = min(24, (int)((sqrtf(wrad) - 1.0f) * 0.5f) + 2);
        float2 up = CsB[24 + m];
        float2 dn = CsB[24 - m];
        const float4* sup = SDB + (24 + m) * 24;
        const float4* sdn = SDB + (24 - m) * 24;
        float sgn = -1.f;
        #pragma unroll 4
        for (int mb = 0; mb < qe; mb++) {
            float4 su = sup[mb]; float4 sd = sdn[mb];
            up.x = fmaf(sgn, su.x, up.x); up.y = fmaf(sgn, su.y, up.y);
            dn.x = fmaf(sgn, sd.x, dn.x); dn.y = fmaf(sgn, sd.y, dn.y);
            sgn = -sgn;
        }
        if (m == 0) {
            G0[128] = up;
        } else {
            SGDG[(m - 1) * GSTRIDE + 128] =
                make_float4(up.x + dn.x, up.y + dn.y,
                            up.y - dn.y, up.x - dn.x);
        }
    }
    __syncthreads();

    // ---- Phase C: crop (u-folded, 18 units, tile 4)
    //              + adaptive max-window sized by |z| (tile 8) ----
    // peak displacement ~3.2 px per unit |z|; radius 12 + 6|z| has >3x margin
    // and reproduces the validated 80x96 window at the clamp.
    const int iu = (int)(((unsigned)__float2int_rn(x)) & 255u);
    const int iv = (int)(((unsigned)__float2int_rn(y)) & 255u);
    const float az = fabsf(z);
    const float ru = fminf(40.0f, 12.0f + 6.0f * az);
    const float rv = fminf(48.0f, 12.0f + 6.0f * az);
    const int nu = (int)ceilf(ru * 0.25f);        // u tiles of 8 (extent 8*nu)
    const int nv = (int)ceilf(rv * (1.0f / 16.0f)); // v blocks of 32
    const int nunits = 18 + nu * nv;              // <= 48
    const int wu0 = (iu - 4 * nu) & 255;
    const int wv0 = (iv - 16 * nv) & 255;

    float lmax = 0.0f;
    const char* wp = (const char*)Wp;

    for (int i = 0; i < 2; i++) {
        int t = warp + 32 * i;
        if (t >= nunits) break;

        if (t < 18) {
            // ---- crop unit: ut 0..8 -> u0 = 4*ut; vb 0..1 ----
            int ut = t >> 1;
            int vb = t & 1;
            int v  = vb ? (224 + lane) : lane;
            int u0 = ut << 2;

            int o0 = ((u0 + 0) << 4) & 4095, o1 = ((u0 + 1) << 4) & 4095;
            int o2 = ((u0 + 2) << 4) & 4095, o3 = ((u0 + 3) << 4) & 4095;
            ull c0 = 0, s0 = 0, c1 = 0, s1 = 0;
            ull c2 = 0, s2 = 0, c3 = 0, s3 = 0;

            const char* gp = (const char*)(SGDG + v);
            #pragma unroll 4
            for (int m = 1; m <= 24; m++) {
                ulonglong2 gsd = *(const ulonglong2*)gp;
                gp += GSTRIDE * 16;
                ulonglong2 w0 = *(const ulonglong2*)(wp + o0);
                ulonglong2 w1 = *(const ulonglong2*)(wp + o1);
                ulonglong2 w2 = *(const ulonglong2*)(wp + o2);
                ulonglong2 w3 = *(const ulonglong2*)(wp + o3);
                FMA2(c0, w0.x, gsd.x, c0); FMA2(s0, w0.y, gsd.y, s0);
                FMA2(c1, w1.x, gsd.x, c1); FMA2(s1, w1.y, gsd.y, s1);
                FMA2(c2, w2.x, gsd.x, c2); FMA2(s2, w2.y, gsd.y, s2);
                FMA2(c3, w3.x, gsd.x, c3); FMA2(s3, w3.y, gsd.y, s3);
                o0 = (o0 + ((u0 + 0) << 4)) & 4095;
                o1 = (o1 + ((u0 + 1) << 4)) & 4095;
                o2 = (o2 + ((u0 + 2) << 4)) & 4095;
                o3 = (o3 + ((u0 + 3) << 4)) & 4095;
            }

            float2 g0 = G0[v];
            int tcol = (v + 32) & 255;

            #pragma unroll
            for (int j = 0; j < 4; j++) {
                ull cj = (j == 0) ? c0 : (j == 1) ? c1 : (j == 2) ? c2 : c3;
                ull sj = (j == 0) ? s0 : (j == 1) ? s1 : (j == 2) ? s2 : s3;
                float2 ac = u2f2(cj);
                float2 as = u2f2(sj);
                float t1r = g0.x + ac.x, t1i = g0.y + ac.y;
                float orx = t1r - as.x, oix = t1i + as.y;   // out(u)
                float prx = t1r + as.x, pix = t1i - as.y;   // out(256-u)
                float p2a = fmaf(orx, orx, oix * oix);
                float p2b = fmaf(prx, prx, pix * pix);
                lmax = fmaxf(lmax, fmaxf(p2a, p2b));
                int u  = u0 + j;
                int sa = (u + 32) & 255;
                if (sa < 64) crop[(sa << 6) + tcol] = p2a;
                int sb = (32 - u) & 255;
                if (sb < 64) crop[(sb << 6) + tcol] = p2b;
            }
        } else {
            // ---- window unit (tile 8): max-only, adaptive extent ----
            int t2  = t - 18;                // 0..nu*nv-1
            int wvb = t2 / nu;               // 0..nv-1
            int wt  = t2 - wvb * nu;         // 0..nu-1
            int vbase = (wv0 + (wvb << 5)) & 255;
            int vidx  = vbase + lane;        // padded index <= 286
            int ub    = wu0 + (wt << 3);

            int st0 = (((ub + 0) & 255) << 4), st1 = (((ub + 1) & 255) << 4);
            int st2 = (((ub + 2) & 255) << 4), st3 = (((ub + 3) & 255) << 4);
            int st4 = (((ub + 4) & 255) << 4), st5 = (((ub + 5) & 255) << 4);
            int st6 = (((ub + 6) & 255) << 4), st7 = (((ub + 7) & 255) << 4);
            int o0 = st0, o1 = st1, o2 = st2, o3 = st3;
            int o4 = st4, o5 = st5, o6 = st6, o7 = st7;
            ull c0 = 0, s0 = 0, c1 = 0, s1 = 0;
            ull c2 = 0, s2 = 0, c3 = 0, s3 = 0;
            ull c4 = 0, s4 = 0, c5 = 0, s5 = 0;
            ull c6 = 0, s6 = 0, c7 = 0, s7 = 0;

            const char* gp = (const char*)(SGDG + vidx);
            #pragma unroll 4
            for (int m = 1; m <= 24; m++) {
                ulonglong2 gsd = *(const ulonglong2*)gp;
                gp += GSTRIDE * 16;
                ulonglong2 w0 = *(const ulonglong2*)(wp + o0);
                ulonglong2 w1 = *(const ulonglong2*)(wp + o1);
                ulonglong2 w2 = *(const ulonglong2*)(wp + o2);
                ulonglong2 w3 = *(const ulonglong2*)(wp + o3);
                FMA2(c0, w0.x, gsd.x, c0); FMA2(s0, w0.y, gsd.y, s0);
                FMA2(c1, w1.x, gsd.x, c1); FMA2(s1, w1.y, gsd.y, s1);
                FMA2(c2, w2.x, gsd.x, c2); FMA2(s2, w2.y, gsd.y, s2);
                FMA2(c3, w3.x, gsd.x, c3); FMA2(s3, w3.y, gsd.y, s3);
                o0 = (o0 + st0) & 4095;
                o1 = (o1 + st1) & 4095;
                o2 = (o2 + st2) & 4095;
                o3 = (o3 + st3) & 4095;
                ulonglong2 w4 = *(const ulonglong2*)(wp + o4);
                ulonglong2 w5 = *(const ulonglong2*)(wp + o5);
                ulonglong2 w6 = *(const ulonglong2*)(wp + o6);
                ulonglong2 w7 = *(const ulonglong2*)(wp + o7);
                FMA2(c4, w4.x, gsd.x, c4); FMA2(s4, w4.y, gsd.y, s4);
                FMA2(c5, w5.x, gsd.x, c5); FMA2(s5, w5.y, gsd.y, s5);
                FMA2(c6, w6.x, gsd.x, c6); FMA2(s6, w6.y, gsd.y, s6);
                FMA2(c7, w7.x, gsd.x, c7); FMA2(s7, w7.y, gsd.y, s7);
                o4 = (o4 + st4) & 4095;
                o5 = (o5 + st5) & 4095;
                o6 = (o6 + st6) & 4095;
                o7 = (o7 + st7) & 4095;
            }

            float2 g0 = G0[vidx];
            float gr = g0.x, gi = g0.y;
            #pragma unroll
            for (int j = 0; j < 8; j++) {
                ull cj, sj;
                switch (j) {
                    case 0: cj = c0; sj = s0; break;
                    case 1: cj = c1; sj = s1; break;
                    case 2: cj = c2; sj = s2; break;
                    case 3: cj = c3; sj = s3; break;
                    case 4: cj = c4; sj = s4; break;
                    case 5: cj = c5; sj = s5; break;
                    case 6: cj = c6; sj = s6; break;
                    default: cj = c7; sj = s7; break;
                }
                float2 ac = u2f2(cj);
                float2 as = u2f2(sj);
                float orx = gr + ac.x - as.x;
                float oix = gi + ac.y + as.y;
                lmax = fmaxf(lmax, fmaf(orx, orx, oix * oix));
            }
        }
    }

    // ---- CTA max reduction ----
    #pragma unroll
    for (int o = 16; o > 0; o >>= 1)
        lmax = fmaxf(lmax, __shfl_xor_sync(0xFFFFFFFFu, lmax, o));
    if (lane == 0) red[warp] = lmax;
    __syncthreads();
    if (warp == 0) {
        float m = red[lane];
        #pragma unroll
        for (int o = 16; o > 0; o >>= 1)
            m = fmaxf(m, __shfl_xor_sync(0xFFFFFFFFu, m, o));
        if (lane == 0) red[0] = m;
    }
    __syncthreads();
    const float maxv = red[0];

    // ---- epilogue: atomic-accumulate (psf/max * A + bg) * mask into out[b] ----
    const float A    = Aa[img];
    const float bg   = Bg[img];
    const float mask = (P[img] > 0.5f) ? 1.0f : 0.0f;
    const float scale = (A / maxv) * mask;
    const float bgm   = bg * mask;
    float* outb = out + (size_t)(img >> 2) * 4096;
    #pragma unroll
    for (int k = 0; k < 4; k++) {
        int idx = tid + k * NTHREADS;
        atomicAdd(&outb[idx], fmaf(crop[idx], scale, bgm));
    }
}

extern "C" void kernel_launch(void* const* d_in, const int* in_sizes, int n_in,
                              void* d_out, int out_size)
{
    (void)in_sizes; (void)n_in;
    cudaMemsetAsync(d_out, 0, (size_t)out_size * sizeof(float));
    cudaFuncSetAttribute(render_kernel,
                         cudaFuncAttributeMaxDynamicSharedMemorySize, SM_TOTAL);
    render_kernel<<<NIMG, NTHREADS, SM_TOTAL>>>(
        (const float*)d_in[0], (const float*)d_in[1], (const float*)d_in[2],
        (const float*)d_in[3], (const float*)d_in[4], (const float*)d_in[5],
        (const float*)d_in[6], (float*)d_out);
}

// round 11
// speedup vs baseline: 1.6404x; 1.0988x over previous
#include <cuda_runtime.h>
#include <math.h>

#define NIMG 256        // B*N = 64*4
#define NT 512
#define NWARP 16

typedef unsigned long long ull;

// ---- dynamic shared layout (bytes), compact-column SGDG (160 slots) ----
// slots 0..63   : crop columns, slot = tcol = (v+32)&255
// slots 64..159 : window blocks, slot = 64 + 32*wvb + lane
#define SM_CSB  0                    // float2 [49]            = 512 (padded)
#define SM_SDB  (SM_CSB + 512)       // float4 [49][24]        = 18816
#define SM_WT   (SM_SDB + 18816)     // float2 [256]           = 2048
#define SM_WP   (SM_WT + 2048)       // ulonglong2 [256]       = 4096
#define SM_SGDG (SM_WP + 4096)       // float4 [24][160]       = 61440
#define SM_G0   (SM_SGDG + 61440)    // float2 [160]           = 1280
#define SM_CROP (SM_G0 + 1280)       // float  [4096]          = 16384
#define SM_RED  (SM_CROP + 16384)    // float  [16]            = 64
#define SM_TOTAL (SM_RED + 64)       // 104640 bytes (~102.2 KB)

#define SGSTRIDE 160

extern __shared__ char smem_raw[];

#define FMA2(d, a, b, c) \
    asm("fma.rn.f32x2 %0, %1, %2, %3;" : "=l"(d) : "l"(a), "l"(b), "l"(c))

__device__ __forceinline__ float2 u2f2(ull v) {
    float2 r;
    asm("mov.b64 {%0, %1}, %2;" : "=f"(r.x), "=f"(r.y) : "l"(v));
    return r;
}
__device__ __forceinline__ ull splat2(float f) {
    ull r;
    asm("mov.b64 %0, {%1, %1};" : "=l"(r) : "f"(f));
    return r;
}

__device__ __forceinline__ float2 pupil_pt(int a, int b, float x, float y,
                                           float z, const float* __restrict__ ph)
{
    float us = (float)(2 * a - 63) * (1.0f / 47.25f);
    float vs = (float)(2 * b - 63) * (1.0f / 47.25f);
    float R  = sqrtf(us * us + vs * vs);
    if (R > 1.0f) return make_float2(0.0f, 0.0f);
    float prop = sqrtf(fmaxf(1.0f - R * R, 0.0f));
    float psi = ph[a * 64 + b] + prop * z
              - (6.283185307179586f / 256.0f)
                * ((float)(a - 32) * x + (float)(b - 32) * y);
    float sn, cs;
    __sincosf(psi, &sn, &cs);
    return make_float2(cs, sn);
}

__device__ __forceinline__ int qe_of(int m) {
    int mm = 2 * m - 1;
    float wrad = 2232.5625f - (float)(mm * mm);
    return min(24, (int)((sqrtf(wrad) - 1.0f) * 0.5f) + 2);
}

__global__ void __launch_bounds__(NT, 2)
render_kernel(const float* __restrict__ X,  const float* __restrict__ Y,
              const float* __restrict__ Z,  const float* __restrict__ Aa,
              const float* __restrict__ Bg, const float* __restrict__ P,
              const float* __restrict__ phase0,
              float* __restrict__ out)
{
    float2*     CsB  = (float2*)    (smem_raw + SM_CSB);
    float4*     SDB  = (float4*)    (smem_raw + SM_SDB);
    float2*     Wt   = (float2*)    (smem_raw + SM_WT);
    ulonglong2* Wp   = (ulonglong2*)(smem_raw + SM_WP);
    float4*     SGDG = (float4*)    (smem_raw + SM_SGDG);
    float2*     G0   = (float2*)    (smem_raw + SM_G0);
    float*      crop = (float*)     (smem_raw + SM_CROP);
    float*      red  = (float*)     (smem_raw + SM_RED);

    const int img  = blockIdx.x;
    const int tid  = threadIdx.x;
    const int lane = tid & 31;
    const int warp = tid >> 5;     // 0..15

    const float x = X[img], y = Y[img], z = Z[img];

    // ---- adaptive window geometry (uniform per CTA) ----
    const int iu = (int)(((unsigned)__float2int_rn(x)) & 255u);
    const int iv = (int)(((unsigned)__float2int_rn(y)) & 255u);
    const float az = fabsf(z);
    const float ru = fminf(40.0f, 12.0f + 6.0f * az);
    const float rv = fminf(48.0f, 12.0f + 6.0f * az);
    const int nu = (int)ceilf(ru * 0.25f);          // u tiles of 8
    const int nv = (int)ceilf(rv * (1.0f / 16.0f)); // v blocks of 32 (<=3)
    const int wu0 = (iu - 4 * nu) & 255;
    const int wv0 = (iv - 16 * nv) & 255;

    // ---- twiddle tables: W[k] = exp(2*pi*i*k/256) ----
    if (tid < 256) {
        float s, c;
        sincospif((float)tid * (1.0f / 128.0f), &s, &c);
        Wt[tid] = make_float2(c, s);
        Wp[tid] = make_ulonglong2(splat2(c), splat2(s));
    }

    // ---- fused Phase A + SDB ----
    for (int idx = tid; idx < 49 * 25; idx += NT) {
        int r = idx / 25;
        int q = idx - r * 25;               // 0..24
        int a = r + 8;
        if (q == 0) {
            CsB[r] = pupil_pt(a, 32, x, y, z, phase0);
        } else {
            float2 cu = pupil_pt(a, 32 + q, x, y, z, phase0);
            float2 cd = pupil_pt(a, 32 - q, x, y, z, phase0);
            SDB[r * 24 + (q - 1)] = make_float4(cu.x + cd.x, cu.y + cd.y,
                                                cu.y - cd.y, cu.x - cd.x);
        }
    }
    __syncthreads();

    // ---- Phase B: compact columns only ----
    // units: t<25 -> crop-fold (m=t, lanes v=0..31, fold covers tcol 1..63)
    //        t<25*(1+nv) -> window-direct, m=(t-25)%25, wvb=(t-25)/25
    //        t==25*(1+nv) -> scalar v=224 unit (tcol slot 0)
    const int nb_win = 25 * nv;
    const int nb_tot = 25 + nb_win + 1;
    for (int i = 0; ; i++) {
        int t = warp + NWARP * i;
        if (t >= nb_tot) break;

        if (t < 25 + nb_win) {
            int m, slot_lo, v;
            bool is_crop = (t < 25);
            if (is_crop) {
                m = t;
                v = lane;                           // 0..31
                slot_lo = 32 + lane;                // tcol(v)
            } else {
                int t2 = t - 25;
                int wvb = t2 / 25;
                m = t2 - 25 * wvb;
                v = (wv0 + (wvb << 5) + lane) & 255;
                slot_lo = 64 + (wvb << 5) + lane;
            }
            int qe = qe_of(m);

            float2 w0 = Wt[v];
            ull CC  = splat2(w0.x), SS  = splat2(w0.y);
            ull RC  = CC,           RS  = SS;
            ull NRS = splat2(-w0.y);
            const ull ZERO = 0;

            ull ACu = 0, ASu = 0, ACd = 0, ASd = 0;
            const ulonglong2* sup = (const ulonglong2*)(SDB + (24 + m) * 24);
            const ulonglong2* sdn = (const ulonglong2*)(SDB + (24 - m) * 24);

            if (m == 0) {
                #pragma unroll 4
                for (int mb = 0; mb < qe; mb++) {
                    ulonglong2 sv = sup[mb];
                    FMA2(ACu, CC, sv.x, ACu);
                    FMA2(ASu, SS, sv.y, ASu);
                    ull t1, t2;
                    FMA2(t1, CC, RC, ZERO); FMA2(t2, CC, RS, ZERO);
                    FMA2(CC, SS, NRS, t1);  FMA2(SS, SS, RC, t2);
                }
                float2 ac = u2f2(ACu), as = u2f2(ASu);
                float2 base = CsB[24];
                float2 glo = make_float2(base.x + ac.x - as.x,
                                         base.y + ac.y + as.y);
                G0[slot_lo] = glo;
                if (is_crop) {
                    float2 ghi = make_float2(base.x + ac.x + as.x,
                                             base.y + ac.y - as.y);
                    G0[32 - v] = (v == 0) ? glo : ghi;
                }
            } else {
                #pragma unroll 4
                for (int mb = 0; mb < qe; mb++) {
                    ulonglong2 sv = sup[mb];
                    ulonglong2 dv = sdn[mb];
                    FMA2(ACu, CC, sv.x, ACu);
                    FMA2(ASu, SS, sv.y, ASu);
                    FMA2(ACd, CC, dv.x, ACd);
                    FMA2(ASd, SS, dv.y, ASd);
                    ull t1, t2;
                    FMA2(t1, CC, RC, ZERO); FMA2(t2, CC, RS, ZERO);
                    FMA2(CC, SS, NRS, t1);  FMA2(SS, SS, RC, t2);
                }
                float2 acu = u2f2(ACu), asu = u2f2(ASu);
                float2 acd = u2f2(ACd), asd = u2f2(ASd);
                float2 bu = CsB[24 + m];
                float2 bd = CsB[24 - m];
                float2 up_lo = make_float2(bu.x + acu.x - asu.x,
                                           bu.y + acu.y + asu.y);
                float2 dn_lo = make_float2(bd.x + acd.x - asd.x,
                                           bd.y + acd.y + asd.y);
                int base = (m - 1) * SGSTRIDE;
                float4 lo4 = make_float4(up_lo.x + dn_lo.x, up_lo.y + dn_lo.y,
                                         up_lo.y - dn_lo.y, up_lo.x - dn_lo.x);
                SGDG[base + slot_lo] = lo4;
                if (is_crop) {
                    float2 up_hi = make_float2(bu.x + acu.x + asu.x,
                                               bu.y + acu.y - asu.y);
                    float2 dn_hi = make_float2(bd.x + acd.x + asd.x,
                                               bd.y + acd.y - asd.y);
                    float4 hi4 = make_float4(up_hi.x + dn_hi.x,
                                             up_hi.y + dn_hi.y,
                                             up_hi.y - dn_hi.y,
                                             up_hi.x - dn_hi.x);
                    SGDG[base + 32 - v] = (v == 0) ? lo4 : hi4;
                }
            }
        } else if (lane < 25) {
            // ---- scalar v=224 column (tcol slot 0), lane = m ----
            int m = lane;
            int qe = qe_of(m);
            float2 wv = Wt[224];
            float wc = wv.x, ws = wv.y;
            float rc = wc, rs = ws;
            float a1u = 0, a2u = 0, a3u = 0, a4u = 0;
            float a1d = 0, a2d = 0, a3d = 0, a4d = 0;
            const float4* sup = SDB + (24 + m) * 24;
            const float4* sdn = SDB + (24 - m) * 24;
            for (int q = 0; q < qe; q++) {
                float4 s = sup[q];
                a1u = fmaf(wc, s.x, a1u); a2u = fmaf(wc, s.y, a2u);
                a3u = fmaf(ws, s.z, a3u); a4u = fmaf(ws, s.w, a4u);
                float4 d = sdn[q];
                a1d = fmaf(wc, d.x, a1d); a2d = fmaf(wc, d.y, a2d);
                a3d = fmaf(ws, d.z, a3d); a4d = fmaf(ws, d.w, a4d);
                float nc = fmaf(wc, rc, -(ws * rs));
                float ns = fmaf(wc, rs,  (ws * rc));
                wc = nc; ws = ns;
            }
            float2 bu = CsB[24 + m];
            float2 bd = CsB[24 - m];
            float2 up = make_float2(bu.x + a1u - a3u, bu.y + a2u + a4u);
            float2 dn = make_float2(bd.x + a1d - a3d, bd.y + a2d + a4d);
            if (m == 0) {
                G0[0] = up;
            } else {
                SGDG[(m - 1) * SGSTRIDE] =
                    make_float4(up.x + dn.x, up.y + dn.y,
                                up.y - dn.y, up.x - dn.x);
            }
        }
    }
    __syncthreads();

    // ---- Phase C: crop (18 units, tile 4, u-fold) + window (nu*nv, tile 8) ----
    const int nunits = 18 + nu * nv;
    float lmax = 0.0f;
    const char* wp = (const char*)Wp;

    for (int i = 0; ; i++) {
        int t = warp + NWARP * i;
        if (t >= nunits) break;

        if (t < 18) {
            // ---- crop unit: ut 0..8 -> u0 = 4*ut; vb 0..1; slot = tcol ----
            int ut = t >> 1;
            int vb = t & 1;
            int slot = (vb << 5) + lane;    // tcol 0..63
            int u0 = ut << 2;

            int o0 = ((u0 + 0) << 4) & 4095, o1 = ((u0 + 1) << 4) & 4095;
            int o2 = ((u0 + 2) << 4) & 4095, o3 = ((u0 + 3) << 4) & 4095;
            ull c0 = 0, s0 = 0, c1 = 0, s1 = 0;
            ull c2 = 0, s2 = 0, c3 = 0, s3 = 0;

            const char* gp = (const char*)(SGDG + slot);
            #pragma unroll 4
            for (int m = 1; m <= 24; m++) {
                ulonglong2 gsd = *(const ulonglong2*)gp;
                gp += SGSTRIDE * 16;
                ulonglong2 w0 = *(const ulonglong2*)(wp + o0);
                ulonglong2 w1 = *(const ulonglong2*)(wp + o1);
                ulonglong2 w2 = *(const ulonglong2*)(wp + o2);
                ulonglong2 w3 = *(const ulonglong2*)(wp + o3);
                FMA2(c0, w0.x, gsd.x, c0); FMA2(s0, w0.y, gsd.y, s0);
                FMA2(c1, w1.x, gsd.x, c1); FMA2(s1, w1.y, gsd.y, s1);
                FMA2(c2, w2.x, gsd.x, c2); FMA2(s2, w2.y, gsd.y, s2);
                FMA2(c3, w3.x, gsd.x, c3); FMA2(s3, w3.y, gsd.y, s3);
                o0 = (o0 + ((u0 + 0) << 4)) & 4095;
                o1 = (o1 + ((u0 + 1) << 4)) & 4095;
                o2 = (o2 + ((u0 + 2) << 4)) & 4095;
                o3 = (o3 + ((u0 + 3) << 4)) & 4095;
            }

            float2 g0 = G0[slot];
            #pragma unroll
            for (int j = 0; j < 4; j++) {
                ull cj = (j == 0) ? c0 : (j == 1) ? c1 : (j == 2) ? c2 : c3;
                ull sj = (j == 0) ? s0 : (j == 1) ? s1 : (j == 2) ? s2 : s3;
                float2 ac = u2f2(cj);
                float2 as = u2f2(sj);
                float t1r = g0.x + ac.x, t1i = g0.y + ac.y;
                float orx = t1r - as.x, oix = t1i + as.y;   // out(u)
                float prx = t1r + as.x, pix = t1i - as.y;   // out(256-u)
                float p2a = fmaf(orx, orx, oix * oix);
                float p2b = fmaf(prx, prx, pix * pix);
                lmax = fmaxf(lmax, fmaxf(p2a, p2b));
                int u  = u0 + j;
                int sa = (u + 32) & 255;
                if (sa < 64) crop[(sa << 6) + slot] = p2a;
                int sb = (32 - u) & 255;
                if (sb < 64) crop[(sb << 6) + slot] = p2b;
            }
        } else {
            // ---- window unit (tile 8): max-only ----
            int t2  = t - 18;
            int wvb = t2 / nu;
            int wt  = t2 - wvb * nu;
            int slot = 64 + (wvb << 5) + lane;
            int ub   = wu0 + (wt << 3);

            int st0 = (((ub + 0) & 255) << 4), st1 = (((ub + 1) & 255) << 4);
            int st2 = (((ub + 2) & 255) << 4), st3 = (((ub + 3) & 255) << 4);
            int st4 = (((ub + 4) & 255) << 4), st5 = (((ub + 5) & 255) << 4);
            int st6 = (((ub + 6) & 255) << 4), st7 = (((ub + 7) & 255) << 4);
            int o0 = st0, o1 = st1, o2 = st2, o3 = st3;
            int o4 = st4, o5 = st5, o6 = st6, o7 = st7;
            ull c0 = 0, s0 = 0, c1 = 0, s1 = 0;
            ull c2 = 0, s2 = 0, c3 = 0, s3 = 0;
            ull c4 = 0, s4 = 0, c5 = 0, s5 = 0;
            ull c6 = 0, s6 = 0, c7 = 0, s7 = 0;

            const char* gp = (const char*)(SGDG + slot);
            #pragma unroll 4
            for (int m = 1; m <= 24; m++) {
                ulonglong2 gsd = *(const ulonglong2*)gp;
                gp += SGSTRIDE * 16;
                ulonglong2 w0 = *(const ulonglong2*)(wp + o0);
                ulonglong2 w1 = *(const ulonglong2*)(wp + o1);
                ulonglong2 w2 = *(const ulonglong2*)(wp + o2);
                ulonglong2 w3 = *(const ulonglong2*)(wp + o3);
                FMA2(c0, w0.x, gsd.x, c0); FMA2(s0, w0.y, gsd.y, s0);
                FMA2(c1, w1.x, gsd.x, c1); FMA2(s1, w1.y, gsd.y, s1);
                FMA2(c2, w2.x, gsd.x, c2); FMA2(s2, w2.y, gsd.y, s2);
                FMA2(c3, w3.x, gsd.x, c3); FMA2(s3, w3.y, gsd.y, s3);
                o0 = (o0 + st0) & 4095;
                o1 = (o1 + st1) & 4095;
                o2 = (o2 + st2) & 4095;
                o3 = (o3 + st3) & 4095;
                ulonglong2 w4 = *(const ulonglong2*)(wp + o4);
                ulonglong2 w5 = *(const ulonglong2*)(wp + o5);
                ulonglong2 w6 = *(const ulonglong2*)(wp + o6);
                ulonglong2 w7 = *(const ulonglong2*)(wp + o7);
                FMA2(c4, w4.x, gsd.x, c4); FMA2(s4, w4.y, gsd.y, s4);
                FMA2(c5, w5.x, gsd.x, c5); FMA2(s5, w5.y, gsd.y, s5);
                FMA2(c6, w6.x, gsd.x, c6); FMA2(s6, w6.y, gsd.y, s6);
                FMA2(c7, w7.x, gsd.x, c7); FMA2(s7, w7.y, gsd.y, s7);
                o4 = (o4 + st4) & 4095;
                o5 = (o5 + st5) & 4095;
                o6 = (o6 + st6) & 4095;
                o7 = (o7 + st7) & 4095;
            }

            float2 g0 = G0[slot];
            float gr = g0.x, gi = g0.y;
            #pragma unroll
            for (int j = 0; j < 8; j++) {
                ull cj, sj;
                switch (j) {
                    case 0: cj = c0; sj = s0; break;
                    case 1: cj = c1; sj = s1; break;
                    case 2: cj = c2; sj = s2; break;
                    case 3: cj = c3; sj = s3; break;
                    case 4: cj = c4; sj = s4; break;
                    case 5: cj = c5; sj = s5; break;
                    case 6: cj = c6; sj = s6; break;
                    default: cj = c7; sj = s7; break;
                }
                float2 ac = u2f2(cj);
                float2 as = u2f2(sj);
                float orx = gr + ac.x - as.x;
                float oix = gi + ac.y + as.y;
                lmax = fmaxf(lmax, fmaf(orx, orx, oix * oix));
            }
        }
    }

    // ---- CTA max reduction (16 warps) ----
    #pragma unroll
    for (int o = 16; o > 0; o >>= 1)
        lmax = fmaxf(lmax, __shfl_xor_sync(0xFFFFFFFFu, lmax, o));
    if (lane == 0) red[warp] = lmax;
    __syncthreads();
    if (warp == 0) {
        float m = (lane < NWARP) ? red[lane] : 0.0f;
        #pragma unroll
        for (int o = 8; o > 0; o >>= 1)
            m = fmaxf(m, __shfl_xor_sync(0xFFFFFFFFu, m, o));
        if (lane == 0) red[0] = m;
    }
    __syncthreads();
    const float maxv = red[0];

    // ---- epilogue: atomic-accumulate (psf/max * A + bg) * mask into out[b] ----
    const float A    = Aa[img];
    const float bg   = Bg[img];
    const float mask = (P[img] > 0.5f) ? 1.0f : 0.0f;
    const float scale = (A / maxv) * mask;
    const float bgm   = bg * mask;
    float* outb = out + (size_t)(img >> 2) * 4096;
    #pragma unroll
    for (int k = 0; k < 8; k++) {
        int idx = tid + k * NT;
        atomicAdd(&outb[idx], fmaf(crop[idx], scale, bgm));
    }
}

extern "C" void kernel_launch(void* const* d_in, const int* in_sizes, int n_in,
                              void* d_out, int out_size)
{
    (void)in_sizes; (void)n_in;
    cudaMemsetAsync(d_out, 0, (size_t)out_size * sizeof(float));
    cudaFuncSetAttribute(render_kernel,
                         cudaFuncAttributeMaxDynamicSharedMemorySize, SM_TOTAL);
    render_kernel<<<NIMG, NT, SM_TOTAL>>>(
        (const float*)d_in[0], (const float*)d_in[1], (const float*)d_in[2],
        (const float*)d_in[3], (const float*)d_in[4], (const float*)d_in[5],
        (const float*)d_in[6], (float*)d_out);
}